// round 10
// baseline (speedup 1.0000x reference)
#include <cuda_runtime.h>

// TensorProductLayer, warp-autonomous: each warp owns 32 consecutive pairs
// end-to-end with a private smem slice and its own cp.async group. No block
// barriers at all -> warps free-run, keeping DRAM continuously fed.
//  - stage: cp.async.cg 16B (208 f4/warp, 7 predicated passes)
//  - compute: 1 pair/lane from warp smem (strides 3,9 coprime to 32: conflict-free)
//  - results overwrite the warp slice; cooperative per-warp STG.128 (104 f4)
// Per pair: a=x0, b=y0, u=x1(3), v=y1(3), A=x2(9), B=y2(9)
//   out0      = a*b + u.v + <A,B>_F
//   out1[i]   = a*v[i] + b*u[i] + (u^T B)[i] + (A v)[i]
//   out2[i,j] = a*B[i,j] + b*A[i,j] + u[i]*v[j] + (A B)[i,j]

#define TPB 256          // 8 warps per block
#define WARP_F4 208      // f4 per warp slice
// warp-slice f4 offsets:    sa 0, sb 8,  su 16,  sv 40,  A 64,  B 136
// warp-slice float offsets: sa 0, sb 32, su 64, sv 160, A 256, B 544

__device__ __forceinline__ void cp16(float4* smem_dst, const float4* gmem_src)
{
    unsigned saddr = (unsigned)__cvta_generic_to_shared(smem_dst);
    asm volatile("cp.async.cg.shared.global [%0], [%1], 16;"
                 :: "r"(saddr), "l"(gmem_src));
}

__device__ __forceinline__ void tp_pair(
    float a, float b,
    const float* __restrict__ u, const float* __restrict__ v,
    const float* __restrict__ A, const float* __restrict__ B,
    float* __restrict__ r0, float* __restrict__ r1, float* __restrict__ r2)
{
    float s0 = a * b;
#pragma unroll
    for (int i = 0; i < 3; ++i) s0 = fmaf(u[i], v[i], s0);
#pragma unroll
    for (int i = 0; i < 9; ++i) s0 = fmaf(A[i], B[i], s0);
    *r0 = s0;

#pragma unroll
    for (int i = 0; i < 3; ++i) {
        float t = a * v[i];
        t = fmaf(b, u[i], t);
#pragma unroll
        for (int d = 0; d < 3; ++d) t = fmaf(u[d], B[d * 3 + i], t);
#pragma unroll
        for (int e = 0; e < 3; ++e) t = fmaf(A[i * 3 + e], v[e], t);
        r1[i] = t;
    }

#pragma unroll
    for (int i = 0; i < 3; ++i) {
#pragma unroll
        for (int j = 0; j < 3; ++j) {
            float t = a * B[i * 3 + j];
            t = fmaf(b, A[i * 3 + j], t);
            t = fmaf(u[i], v[j], t);
#pragma unroll
            for (int e = 0; e < 3; ++e) t = fmaf(A[i * 3 + e], B[e * 3 + j], t);
            r2[i * 3 + j] = t;
        }
    }
}

__global__ void __launch_bounds__(TPB)
tp_kernel_warp(const float* __restrict__ x0f, const float* __restrict__ y0f,
               const float* __restrict__ x1f, const float* __restrict__ y1f,
               const float* __restrict__ x2f, const float* __restrict__ y2f,
               float* __restrict__ o0f, float* __restrict__ o1f, float* __restrict__ o2f,
               int total)
{
    __shared__ float4 sbuf[8 * WARP_F4];   // 26,624 B -> 8 CTAs/SM

    const int tid  = threadIdx.x;
    const int lane = tid & 31;
    const int warp = tid >> 5;
    const int pair0 = blockIdx.x * TPB + warp * 32;   // this warp's 32 pairs

    float4* wb = sbuf + warp * WARP_F4;

    const float4* x0 = reinterpret_cast<const float4*>(x0f);
    const float4* y0 = reinterpret_cast<const float4*>(y0f);
    const float4* x1 = reinterpret_cast<const float4*>(x1f);
    const float4* y1 = reinterpret_cast<const float4*>(y1f);
    const float4* x2 = reinterpret_cast<const float4*>(x2f);
    const float4* y2 = reinterpret_cast<const float4*>(y2f);
    float4* o0 = reinterpret_cast<float4*>(o0f);
    float4* o1 = reinterpret_cast<float4*>(o1f);
    float4* o2 = reinterpret_cast<float4*>(o2f);

    if (pair0 + 32 <= total) {
        // ================= fast path: full warp tile =================
        const int g = pair0 >> 2;          // f4 index in rank-0 space
        const int g3 = g * 3, g9 = g * 9;

        // ---- stage 208 f4 via cp.async: 7 passes of 32 lanes ----
#pragma unroll
        for (int k = 0; k < 7; ++k) {
            int i = lane + 32 * k;
            if (i < WARP_F4) {
                const float4* src;
                if (i < 8)        src = x0 + (g  + i);
                else if (i < 16)  src = y0 + (g  + i - 8);
                else if (i < 40)  src = x1 + (g3 + i - 16);
                else if (i < 64)  src = y1 + (g3 + i - 40);
                else if (i < 136) src = x2 + (g9 + i - 64);
                else              src = y2 + (g9 + i - 136);
                cp16(wb + i, src);
            }
        }
        asm volatile("cp.async.commit_group;");
        asm volatile("cp.async.wait_group 0;");
        __syncwarp();

        // ---- compute: lane = pair, from warp slice ----
        {
            float* f = reinterpret_cast<float*>(wb);
            float a = f[lane], b = f[32 + lane];
            float u[3], v[3], A[9], B[9];
#pragma unroll
            for (int i = 0; i < 3; ++i) { u[i] = f[64 + lane * 3 + i]; v[i] = f[160 + lane * 3 + i]; }
#pragma unroll
            for (int i = 0; i < 9; ++i) { A[i] = f[256 + lane * 9 + i]; B[i] = f[544 + lane * 9 + i]; }

            float r0, r1[3], r2[9];
            tp_pair(a, b, u, v, A, B, &r0, r1, r2);

            f[lane] = r0;
#pragma unroll
            for (int i = 0; i < 3; ++i) f[64 + lane * 3 + i] = r1[i];
#pragma unroll
            for (int i = 0; i < 9; ++i) f[256 + lane * 9 + i] = r2[i];
        }
        __syncwarp();

        // ---- store 104 f4: 4 passes of 32 lanes ----
#pragma unroll
        for (int k = 0; k < 4; ++k) {
            int i = lane + 32 * k;
            if (i < 104) {
                if (i < 8)       __stcs(o0 + (g  + i),        wb[i]);
                else if (i < 32) __stcs(o1 + (g3 + i - 8),    wb[16 + (i - 8)]);
                else             __stcs(o2 + (g9 + i - 32),   wb[64 + (i - 32)]);
            }
        }
    } else {
        // ================= tail path: scalar with guards =================
        int p = pair0 + lane;
        if (p < total) {
            float a = x0f[p], b = y0f[p];
            float u[3], v[3], A[9], B[9];
#pragma unroll
            for (int i = 0; i < 3; ++i) { u[i] = x1f[p * 3 + i]; v[i] = y1f[p * 3 + i]; }
#pragma unroll
            for (int i = 0; i < 9; ++i) { A[i] = x2f[p * 9 + i]; B[i] = y2f[p * 9 + i]; }
            float r0, r1[3], r2[9];
            tp_pair(a, b, u, v, A, B, &r0, r1, r2);
            o0f[p] = r0;
#pragma unroll
            for (int i = 0; i < 3; ++i) o1f[p * 3 + i] = r1[i];
#pragma unroll
            for (int i = 0; i < 9; ++i) o2f[p * 9 + i] = r2[i];
        }
    }
}

extern "C" void kernel_launch(void* const* d_in, const int* in_sizes, int n_in,
                              void* d_out, int out_size)
{
    // Resolve inputs by element count: s = base (rank-0), 3s (rank-1), 9s (rank-2).
    // First occurrence of a size = x tensor, second = y tensor (robust to both
    // metadata orderings).
    int s = in_sizes[0];
    for (int i = 1; i < n_in; ++i) if (in_sizes[i] < s) s = in_sizes[i];

    const float* X[3] = {nullptr, nullptr, nullptr};
    const float* Y[3] = {nullptr, nullptr, nullptr};
    for (int i = 0; i < n_in; ++i) {
        int r;
        if (in_sizes[i] == s)          r = 0;
        else if (in_sizes[i] == 3 * s) r = 1;
        else                           r = 2;
        if (X[r] == nullptr) X[r] = (const float*)d_in[i];
        else                 Y[r] = (const float*)d_in[i];
    }

    float* o0 = (float*)d_out;       // s elements
    float* o1 = o0 + (size_t)s;      // 3s elements
    float* o2 = o0 + (size_t)4 * s;  // 9s elements

    int blocks = (s + TPB - 1) / TPB;
    tp_kernel_warp<<<blocks, TPB>>>(X[0], Y[0], X[1], Y[1], X[2], Y[2],
                                    o0, o1, o2, s);
}